// round 13
// baseline (speedup 1.0000x reference)
#include <cuda_runtime.h>
#include <stdint.h>

// TopK_31877247271346: per-row top-64 of x[4096][16384] fp32 scattered into zeros.
// Persistent warp-specialized pipeline: 512 CTAs x 8 rows (single wave).
//  - warps 1..15 (480 thr) stream rows continuously: load, zero-store, SIMD
//    candidate mask (x >= 2.25 via signed hi-16 compare), warp-aggregated
//    compaction into a DOUBLE-BUFFERED smem candidate array
//  - warp 0 overlaps: selects+scatters row r-1 (other buffer) while row r
//    streams; exact 4-round radix + stable lowest-index tie-break
//  - one __syncthreads per row (buffer flip + zero-before-scatter ordering)
// Exact warp-0 fallback via global re-reads if count outside [K, CAP].

#define NROWS 4096
#define NCOLS 16384
#define KSEL  64
#define NT    512
#define GRID  512
#define RPC   (NROWS / GRID)     // 8 rows per CTA
#define CAP   512
#define ST    480                // streaming threads (warps 1..15)
#define REM   256                // leftover uint4: t<256 handle j=3840+t
#define REMBASE 3840             // 8*480

__device__ __forceinline__ uint32_t f2key(uint32_t a) {
    return (a & 0x80000000u) ? ~a : (a | 0x80000000u);
}
__device__ __forceinline__ float key2f(uint32_t u) {
    return __uint_as_float((u & 0x80000000u) ? (u ^ 0x80000000u) : ~u);
}

// 4-bit candidate nibble for one uint4 (bit c set iff element c >= 2.25f).
__device__ __forceinline__ uint32_t cand_nib(uint4 v) {
    uint32_t p0 = __byte_perm(v.x, v.y, 0x7632);   // [y_hi16 : x_hi16]
    uint32_t p1 = __byte_perm(v.z, v.w, 0x7632);   // [w_hi16 : z_hi16]
    uint32_t r0 = __vsetges2(p0, 0x40104010u);     // signed hi16 >= 0x4010
    uint32_t r1 = __vsetges2(p1, 0x40104010u);
    return __dp4a(r1, 0x00080004u, __dp4a(r0, 0x00020001u, 0u));
}

// ---------------- warp-0 exact fallback (correctness-only path) -------------
__device__ void warp_fallback(const float* __restrict__ x,
                              float* __restrict__ out,
                              size_t rowOff, int lane)
{
    unsigned long long blo = 0ull, bhi = 0x100000000ull;
    while (bhi - blo > 1ull) {
        const uint32_t mid = (uint32_t)((blo + bhi) >> 1);
        uint32_t c = 0;
        for (int j = lane; j < NCOLS; j += 32)
            c += (f2key(__float_as_uint(x[rowOff + j])) >= mid);
        c = __reduce_add_sync(0xFFFFFFFFu, c);
        if (c >= KSEL) blo = (unsigned long long)mid;
        else           bhi = (unsigned long long)mid;
    }
    const uint32_t T = (uint32_t)blo;

    uint32_t ca = 0, ce = 0;
    for (int j = lane; j < NCOLS; j += 32) {
        const uint32_t k = f2key(__float_as_uint(x[rowOff + j]));
        ca += (k > T);
        ce += (k == T);
    }
    ca = __reduce_add_sync(0xFFFFFFFFu, ca);
    ce = __reduce_add_sync(0xFFFFFFFFu, ce);
    const uint32_t remK = KSEL - ca;

    uint32_t tieCut = 0xFFFFFFFFu;
    if (ce != remK) {
        int lo = 0, hi = NCOLS - 1;
        while (lo < hi) {
            const int mid = (lo + hi) >> 1;
            uint32_t c = 0;
            for (int j = lane; j < NCOLS; j += 32)
                c += (f2key(__float_as_uint(x[rowOff + j])) == T && j <= mid);
            c = __reduce_add_sync(0xFFFFFFFFu, c);
            if (c >= remK) hi = mid; else lo = mid + 1;
        }
        tieCut = (uint32_t)lo;
    }
    for (int j = lane; j < NCOLS; j += 32) {
        const uint32_t k = f2key(__float_as_uint(x[rowOff + j]));
        if (k > T || (k == T && (uint32_t)j <= tieCut))
            out[rowOff + j] = key2f(k);
    }
}

// ---------------- warp-0 select + scatter over one row's candidates --------
__device__ __forceinline__ void warp_select_scatter(
    const float* __restrict__ x, float* __restrict__ out, size_t rowOff,
    uint32_t nc, const uint32_t* __restrict__ skeyP,
    const uint16_t* __restrict__ scolP, uint32_t* hist, int lane)
{
    if (nc < KSEL || nc > CAP) { warp_fallback(x, out, rowOff, lane); return; }

    #pragma unroll
    for (int j = 0; j < 8; j++) hist[lane * 8 + j] = 0;
    __syncwarp();

    uint32_t prefix = 0, remK = KSEL, cntEq = 0;
    #pragma unroll 1
    for (int shift = 24; shift >= 0; shift -= 8) {
        const uint32_t pmask = (shift == 24) ? 0u : (0xFFFFFFFFu << (shift + 8));
        for (int j = lane; j < (int)nc; j += 32) {
            const uint32_t u = skeyP[j];
            if ((u & pmask) == prefix)
                atomicAdd(&hist[(u >> shift) & 255u], 1u);
        }
        __syncwarp();

        uint32_t local[8], sum = 0;
        #pragma unroll
        for (int j = 0; j < 8; j++) { local[j] = hist[lane*8 + j]; sum += local[j]; }
        #pragma unroll
        for (int j = 0; j < 8; j++) hist[lane*8 + j] = 0;

        uint32_t tot = sum;
        #pragma unroll
        for (int off = 1; off < 32; off <<= 1) {
            uint32_t t = __shfl_down_sync(0xFFFFFFFFu, tot, off);
            if (lane + off < 32) tot += t;
        }
        uint32_t run = tot - sum;
        uint32_t myP = 0, myR = 0, myE = 0;
        bool found = false;
        #pragma unroll
        for (int j = 7; j >= 0; j--) {
            const uint32_t inc = run + local[j];
            if (inc >= remK && run < remK) {          // exactly one (lane,j)
                found = true;
                myP = prefix | ((uint32_t)(lane*8 + j) << shift);
                myR = remK - run;
                myE = local[j];
            }
            run = inc;
        }
        const uint32_t bal = __ballot_sync(0xFFFFFFFFu, found);
        const int src = __ffs(bal) - 1;
        prefix = __shfl_sync(0xFFFFFFFFu, myP, src);
        remK   = __shfl_sync(0xFFFFFFFFu, myR, src);
        cntEq  = __shfl_sync(0xFFFFFFFFu, myE, src);
        __syncwarp();
    }
    const uint32_t T = prefix;

    uint32_t tieCut = 0xFFFFFFFFu;
    if (cntEq != remK) {                   // rare: excess ties at threshold
        int lo = 0, hi = NCOLS - 1;
        while (lo < hi) {
            const int mid = (lo + hi) >> 1;
            uint32_t c = 0;
            for (int j = lane; j < (int)nc; j += 32)
                c += (skeyP[j] == T && (int)scolP[j] <= mid) ? 1u : 0u;
            c = __reduce_add_sync(0xFFFFFFFFu, c);
            if (c >= remK) hi = mid; else lo = mid + 1;
        }
        tieCut = (uint32_t)lo;
    }

    for (int j = lane; j < (int)nc; j += 32) {
        const uint32_t u = skeyP[j];
        const uint32_t col = scolP[j];
        if (u > T || (u == T && col <= tieCut))
            __stcs(&out[rowOff + col], __uint_as_float(u));
    }
}

// ------------------------------- main kernel -------------------------------
__global__ void __launch_bounds__(NT, 4)
topk_persistent_kernel(const float* __restrict__ x, float* __restrict__ out)
{
    __shared__ uint32_t hist[256];
    __shared__ uint32_t nCand[2];
    __shared__ uint32_t skey[2][CAP];
    __shared__ uint16_t scol[2][CAP];

    const int tid  = threadIdx.x;
    const int lane = tid & 31;
    const int wid  = tid >> 5;
    const int row0 = blockIdx.x * RPC;

    if (tid == 0) { nCand[0] = 0; nCand[1] = 0; }
    __syncthreads();

    #pragma unroll 1
    for (int r = 0; r < RPC; r++) {
        const int p = r & 1;
        if (wid != 0) {
            // -------- streaming warps: one full row --------
            const int t = tid - 32;                     // 0..479
            const size_t rowOff = (size_t)(row0 + r) * NCOLS;
            const uint4* __restrict__ xr =
                reinterpret_cast<const uint4*>(x + rowOff);
            uint4* __restrict__ orow = reinterpret_cast<uint4*>(out + rowOff);

            uint4 v[4];
            #pragma unroll
            for (int i = 0; i < 4; i++) v[i] = xr[t + i * ST];

            const uint4 z4 = make_uint4(0u, 0u, 0u, 0u);
            #pragma unroll
            for (int i = 0; i < 8; i++) __stcs(&orow[t + i * ST], z4);
            if (t < REM) __stcs(&orow[REMBASE + t], z4);

            uint32_t m = 0;
            #pragma unroll
            for (int i = 0; i < 4; i++) m |= cand_nib(v[i]) << (4 * i);
            #pragma unroll
            for (int i = 0; i < 4; i++) v[i] = xr[t + (4 + i) * ST];
            #pragma unroll
            for (int i = 0; i < 4; i++) m |= cand_nib(v[i]) << (16 + 4 * i);
            uint32_t m8 = 0;
            if (t < REM) m8 = cand_nib(xr[REMBASE + t]);

            // warp-aggregated compaction into buffer p
            const uint32_t cnt = (uint32_t)(__popc(m) + __popc(m8));
            uint32_t pre = cnt;
            #pragma unroll
            for (int off = 1; off < 32; off <<= 1) {
                uint32_t tt = __shfl_up_sync(0xFFFFFFFFu, pre, off);
                if (lane >= off) pre += tt;
            }
            uint32_t wbase = 0;
            if (lane == 31 && pre) wbase = atomicAdd(&nCand[p], pre);
            wbase = __shfl_sync(0xFFFFFFFFu, wbase, 31);
            uint32_t base = wbase + (pre - cnt);

            uint32_t mm = m;
            while (mm) {
                const int e = __ffs(mm) - 1; mm &= mm - 1;
                const int i = e >> 2, cc = e & 3;
                const uint32_t col = (uint32_t)(t + i * ST) * 4u + (uint32_t)cc;
                if (base < CAP) {
                    skey[p][base] = __float_as_uint(__ldg(x + rowOff + col));
                    scol[p][base] = (uint16_t)col;
                }
                base++;
            }
            while (m8) {
                const int cc = __ffs(m8) - 1; m8 &= m8 - 1;
                const uint32_t col = (uint32_t)(REMBASE + t) * 4u + (uint32_t)cc;
                if (base < CAP) {
                    skey[p][base] = __float_as_uint(__ldg(x + rowOff + col));
                    scol[p][base] = (uint16_t)col;
                }
                base++;
            }
        } else {
            // -------- warp 0: select previous row (other buffer) --------
            if (r > 0) {
                const int q = p ^ 1;
                const size_t prOff = (size_t)(row0 + r - 1) * NCOLS;
                const uint32_t nc = nCand[q];
                warp_select_scatter(x, out, prOff, nc, skey[q], scol[q],
                                    hist, lane);
                __syncwarp();
                if (lane == 0) nCand[q] = 0;     // ready for row r+1
            }
        }
        __syncthreads();                          // buffer flip + ordering
    }

    // final row's select (buffer (RPC-1)&1)
    if (wid == 0) {
        const int q = (RPC - 1) & 1;
        const size_t prOff = (size_t)(row0 + RPC - 1) * NCOLS;
        warp_select_scatter(x, out, prOff, nCand[q], skey[q], scol[q],
                            hist, lane);
    }
}

extern "C" void kernel_launch(void* const* d_in, const int* in_sizes, int n_in,
                              void* d_out, int out_size)
{
    const float* x = (const float*)d_in[0];
    float* out = (float*)d_out;
    (void)in_sizes; (void)n_in; (void)out_size;

    topk_persistent_kernel<<<GRID, NT>>>(x, out);
}